// round 3
// baseline (speedup 1.0000x reference)
#include <cuda_runtime.h>
#include <cstdint>

#define NN 50000
#define EE 800000
#define IN_F 128
#define HF 64
#define HEADS 4
#define HC 256            // HEADS*HF (projected row width, both layers)
#define NEG_SLOPE 0.2f

// ---------------- device scratch (no allocations allowed) ----------------
__device__ __align__(16) float g_h[(size_t)NN * HC];     // projected features
__device__ __align__(16) float g_as[NN * HEADS];         // alpha_src per node/head
__device__ __align__(16) float g_ad[NN * HEADS];         // alpha_dst per node/head
__device__ __align__(16) float g_mid[(size_t)NN * HF];   // layer-1 output after ELU
__device__ int   g_deg[NN];
__device__ int   g_rowptr[NN + 1];
__device__ int   g_cursor[NN];
__device__ int   g_csr[EE];                // src ids grouped by dst
__device__ int   g_is64;                   // edge_index dtype flag

__device__ __forceinline__ float lrelu(float v) { return v > 0.f ? v : NEG_SLOPE * v; }

// ---------------- edge dtype detection ----------------
__global__ void k_flag_init() { g_is64 = 1; }

// Reading the first EE entries as int64 is in-bounds under BOTH layouts
// (int64 buffer: 2*EE entries; int32 buffer: EE int64-sized slots).
// If data is really int32, combined pairs fall outside [0, NN) somewhere.
__global__ void k_detect(const long long* __restrict__ ei) {
    int e = blockIdx.x * blockDim.x + threadIdx.x;
    if (e < EE) {
        long long v = ei[e];
        if (v < 0 || v >= NN) g_is64 = 0;   // benign race: only writes 0
    }
}

// ---------------- CSR build ----------------
__global__ void k_zero_deg() {
    int i = blockIdx.x * blockDim.x + threadIdx.x;
    if (i < NN) g_deg[i] = 0;
}

__global__ void k_hist(const void* __restrict__ eiv) {
    int e = blockIdx.x * blockDim.x + threadIdx.x;
    if (e < EE) {
        int d = g_is64 ? (int)((const long long*)eiv)[EE + e]
                       : ((const int*)eiv)[EE + e];
        if ((unsigned)d < NN) atomicAdd(&g_deg[d], 1);
    }
}

__global__ void k_scan() {
    __shared__ int sm[1024];
    const int t = threadIdx.x;
    const int CH = (NN + 1023) / 1024;   // 49
    const int base = t * CH;
    int s = 0;
    for (int i = 0; i < CH; i++) {
        int idx = base + i;
        if (idx < NN) s += g_deg[idx];
    }
    sm[t] = s;
    __syncthreads();
    for (int off = 1; off < 1024; off <<= 1) {
        int v = (t >= off) ? sm[t - off] : 0;
        __syncthreads();
        sm[t] += v;
        __syncthreads();
    }
    int run = (t > 0) ? sm[t - 1] : 0;
    for (int i = 0; i < CH; i++) {
        int idx = base + i;
        if (idx < NN) { g_rowptr[idx] = run; run += g_deg[idx]; }
    }
    if (t == 0) g_rowptr[NN] = sm[1023];
}

__global__ void k_init_cursor() {
    int i = blockIdx.x * blockDim.x + threadIdx.x;
    if (i < NN) g_cursor[i] = g_rowptr[i];
}

__global__ void k_scatter(const void* __restrict__ eiv) {
    int e = blockIdx.x * blockDim.x + threadIdx.x;
    if (e < EE) {
        int s, d;
        if (g_is64) {
            s = (int)((const long long*)eiv)[e];
            d = (int)((const long long*)eiv)[EE + e];
        } else {
            s = ((const int*)eiv)[e];
            d = ((const int*)eiv)[EE + e];
        }
        if ((unsigned)s < NN && (unsigned)d < NN) {
            int p = atomicAdd(&g_cursor[d], 1);
            g_csr[p] = s;
        }
    }
}

// ---------------- SGEMM: g_h[M,256] = A[M,K] * B[256,K]^T ----------------
// Tile 128x64, BK=16, 256 threads, 8x4 microtile per thread.
template <int K, bool USE_MID>
__global__ void k_sgemm_nt(const float* __restrict__ Ain, const float* __restrict__ B) {
    const float* A = USE_MID ? (const float*)g_mid : Ain;
    __shared__ float As[128][17];
    __shared__ float Bs[64][17];
    const int bm = blockIdx.x * 128;
    const int bn = blockIdx.y * 64;
    const int t  = threadIdx.x;
    const int tx = t & 15;        // 16 cols of threads (N)
    const int ty = t >> 4;        // 16 rows of threads (M)

    float acc[8][4];
#pragma unroll
    for (int i = 0; i < 8; i++)
#pragma unroll
        for (int j = 0; j < 4; j++) acc[i][j] = 0.f;

    const int ar = t >> 2;              // 0..63
    const int ac = (t & 3) * 4;         // 0,4,8,12

#pragma unroll 1
    for (int k0 = 0; k0 < K; k0 += 16) {
#pragma unroll
        for (int r = 0; r < 2; r++) {
            int row = ar + r * 64;
            int gm  = bm + row;
            float4 v = make_float4(0.f, 0.f, 0.f, 0.f);
            if (gm < NN) v = *(const float4*)&A[(size_t)gm * K + k0 + ac];
            As[row][ac + 0] = v.x; As[row][ac + 1] = v.y;
            As[row][ac + 2] = v.z; As[row][ac + 3] = v.w;
        }
        {
            float4 v = *(const float4*)&B[(size_t)(bn + ar) * K + k0 + ac];
            Bs[ar][ac + 0] = v.x; Bs[ar][ac + 1] = v.y;
            Bs[ar][ac + 2] = v.z; Bs[ar][ac + 3] = v.w;
        }
        __syncthreads();
#pragma unroll
        for (int kk = 0; kk < 16; kk++) {
            float a[8], b[4];
#pragma unroll
            for (int i = 0; i < 8; i++) a[i] = As[ty * 8 + i][kk];
#pragma unroll
            for (int j = 0; j < 4; j++) b[j] = Bs[tx * 4 + j][kk];
#pragma unroll
            for (int i = 0; i < 8; i++)
#pragma unroll
                for (int j = 0; j < 4; j++) acc[i][j] = fmaf(a[i], b[j], acc[i][j]);
        }
        __syncthreads();
    }
#pragma unroll
    for (int i = 0; i < 8; i++) {
        int gm = bm + ty * 8 + i;
        if (gm < NN) {
            float4 v = make_float4(acc[i][0], acc[i][1], acc[i][2], acc[i][3]);
            *(float4*)&g_h[(size_t)gm * HC + bn + tx * 4] = v;
        }
    }
}

// ---------------- attention coefficients ----------------
__global__ void k_attn_coef(const float* __restrict__ a_src, const float* __restrict__ a_dst) {
    int warp = (blockIdx.x * blockDim.x + threadIdx.x) >> 5;
    if (warp >= NN) return;
    int lane = threadIdx.x & 31;
    const float4* hp = (const float4*)&g_h[(size_t)warp * HC];
    float4 v0 = hp[lane * 2], v1 = hp[lane * 2 + 1];
    const float4* ap = (const float4*)a_src;
    const float4* bp = (const float4*)a_dst;
    float4 a0 = ap[lane * 2], a1 = ap[lane * 2 + 1];
    float4 b0 = bp[lane * 2], b1 = bp[lane * 2 + 1];
    float s = v0.x * a0.x + v0.y * a0.y + v0.z * a0.z + v0.w * a0.w
            + v1.x * a1.x + v1.y * a1.y + v1.z * a1.z + v1.w * a1.w;
    float d = v0.x * b0.x + v0.y * b0.y + v0.z * b0.z + v0.w * b0.w
            + v1.x * b1.x + v1.y * b1.y + v1.z * b1.z + v1.w * b1.w;
#pragma unroll
    for (int off = 4; off; off >>= 1) {
        s += __shfl_down_sync(0xffffffffu, s, off);
        d += __shfl_down_sync(0xffffffffu, d, off);
    }
    if ((lane & 7) == 0) {
        int h = lane >> 3;
        g_as[warp * 4 + h] = s;
        g_ad[warp * 4 + h] = d;
    }
}

// ---------------- aggregation: per-dst softmax + weighted gather ----------------
template <bool TO_OUT>
__global__ void k_aggregate(const float* __restrict__ bias, float* __restrict__ out) {
    int warp = (blockIdx.x * blockDim.x + threadIdx.x) >> 5;
    if (warp >= NN) return;
    const int n = warp;
    const int lane = threadIdx.x & 31;
    const int beg = g_rowptr[n];
    const int deg = g_rowptr[n + 1] - beg + 1;   // + self loop
    const float4 adn = *(const float4*)&g_ad[n * 4];

    // pass 1: per-head max
    float m0 = -1e30f, m1 = -1e30f, m2 = -1e30f, m3 = -1e30f;
    for (int i = lane; i < deg; i += 32) {
        int s = (i < deg - 1) ? g_csr[beg + i] : n;
        float4 av = *(const float4*)&g_as[s * 4];
        m0 = fmaxf(m0, lrelu(av.x + adn.x));
        m1 = fmaxf(m1, lrelu(av.y + adn.y));
        m2 = fmaxf(m2, lrelu(av.z + adn.z));
        m3 = fmaxf(m3, lrelu(av.w + adn.w));
    }
#pragma unroll
    for (int off = 16; off; off >>= 1) {
        m0 = fmaxf(m0, __shfl_xor_sync(0xffffffffu, m0, off));
        m1 = fmaxf(m1, __shfl_xor_sync(0xffffffffu, m1, off));
        m2 = fmaxf(m2, __shfl_xor_sync(0xffffffffu, m2, off));
        m3 = fmaxf(m3, __shfl_xor_sync(0xffffffffu, m3, off));
    }

    // pass 2: per-head denominator
    float d0 = 0.f, d1 = 0.f, d2 = 0.f, d3 = 0.f;
    for (int i = lane; i < deg; i += 32) {
        int s = (i < deg - 1) ? g_csr[beg + i] : n;
        float4 av = *(const float4*)&g_as[s * 4];
        d0 += __expf(lrelu(av.x + adn.x) - m0);
        d1 += __expf(lrelu(av.y + adn.y) - m1);
        d2 += __expf(lrelu(av.z + adn.z) - m2);
        d3 += __expf(lrelu(av.w + adn.w) - m3);
    }
#pragma unroll
    for (int off = 16; off; off >>= 1) {
        d0 += __shfl_xor_sync(0xffffffffu, d0, off);
        d1 += __shfl_xor_sync(0xffffffffu, d1, off);
        d2 += __shfl_xor_sync(0xffffffffu, d2, off);
        d3 += __shfl_xor_sync(0xffffffffu, d3, off);
    }
    const float r0 = 1.f / (d0 + 1e-16f);
    const float r1 = 1.f / (d1 + 1e-16f);
    const float r2 = 1.f / (d2 + 1e-16f);
    const float r3 = 1.f / (d3 + 1e-16f);

    // pass 3: weighted gather; lane owns channels lane and lane+32
    float acc0 = 0.f, acc1 = 0.f;
    for (int i = 0; i < deg; i++) {
        int s = (i < deg - 1) ? g_csr[beg + i] : n;
        float4 av = *(const float4*)&g_as[s * 4];            // broadcast load
        float w0 = __expf(lrelu(av.x + adn.x) - m0) * r0;
        float w1 = __expf(lrelu(av.y + adn.y) - m1) * r1;
        float w2 = __expf(lrelu(av.z + adn.z) - m2) * r2;
        float w3 = __expf(lrelu(av.w + adn.w) - m3) * r3;
        const float* hs = &g_h[(size_t)s * HC];
        float h00 = hs[lane],        h01 = hs[32 + lane];
        float h10 = hs[64 + lane],   h11 = hs[96 + lane];
        float h20 = hs[128 + lane],  h21 = hs[160 + lane];
        float h30 = hs[192 + lane],  h31 = hs[224 + lane];
        acc0 = fmaf(w0, h00, acc0); acc0 = fmaf(w1, h10, acc0);
        acc0 = fmaf(w2, h20, acc0); acc0 = fmaf(w3, h30, acc0);
        acc1 = fmaf(w0, h01, acc1); acc1 = fmaf(w1, h11, acc1);
        acc1 = fmaf(w2, h21, acc1); acc1 = fmaf(w3, h31, acc1);
    }
    float o0 = acc0 * 0.25f + bias[lane];
    float o1 = acc1 * 0.25f + bias[lane + 32];
    if (!TO_OUT) {   // layer 1: ELU, write g_mid
        o0 = o0 > 0.f ? o0 : expm1f(o0);
        o1 = o1 > 0.f ? o1 : expm1f(o1);
        g_mid[(size_t)n * HF + lane]      = o0;
        g_mid[(size_t)n * HF + 32 + lane] = o1;
    } else {         // layer 2: write harness output
        out[(size_t)n * HF + lane]      = o0;
        out[(size_t)n * HF + 32 + lane] = o1;
    }
}

// ---------------- host launcher (kernel launches ONLY) ----------------
extern "C" void kernel_launch(void* const* d_in, const int* in_sizes, int n_in,
                              void* d_out, int out_size) {
    const float* x   = (const float*)d_in[0];
    const void*  ei  = d_in[1];
    const float* W1  = (const float*)d_in[2];
    const float* as1 = (const float*)d_in[3];
    const float* ad1 = (const float*)d_in[4];
    const float* b1  = (const float*)d_in[5];
    const float* W2  = (const float*)d_in[6];
    const float* as2 = (const float*)d_in[7];
    const float* ad2 = (const float*)d_in[8];
    const float* b2  = (const float*)d_in[9];
    float*       out = (float*)d_out;

    // --- edge dtype detection + CSR build ---
    k_flag_init<<<1, 1>>>();
    k_detect<<<(EE + 255) / 256, 256>>>((const long long*)ei);
    k_zero_deg<<<(NN + 255) / 256, 256>>>();
    k_hist<<<(EE + 255) / 256, 256>>>(ei);
    k_scan<<<1, 1024>>>();
    k_init_cursor<<<(NN + 255) / 256, 256>>>();
    k_scatter<<<(EE + 255) / 256, 256>>>(ei);

    const dim3 gemm_grid((NN + 127) / 128, HC / 64);
    const int  warps_grid = (NN * 32 + 255) / 256;

    // --- layer 1 ---
    k_sgemm_nt<IN_F, false><<<gemm_grid, 256>>>(x, W1);
    k_attn_coef<<<warps_grid, 256>>>(as1, ad1);
    k_aggregate<false><<<warps_grid, 256>>>(b1, nullptr);

    // --- layer 2 ---
    k_sgemm_nt<HF, true><<<gemm_grid, 256>>>(nullptr, W2);
    k_attn_coef<<<warps_grid, 256>>>(as2, ad2);
    k_aggregate<true><<<warps_grid, 256>>>(b2, out);
}

// round 6
// speedup vs baseline: 1.2854x; 1.2854x over previous
#include <cuda_runtime.h>
#include <cuda_bf16.h>
#include <cstdint>

#define NN 50000
#define EE 800000
#define IN_F 128
#define HF 64
#define HEADS 4
#define HC 256            // HEADS*HF
#define NEG_SLOPE 0.2f

// ---------------- device scratch ----------------
__device__ __align__(16) float g_h[(size_t)NN * HC];     // projected features
__device__ __align__(16) float g_as[NN * HEADS];
__device__ __align__(16) float g_ad[NN * HEADS];
__device__ __align__(16) float g_mid[(size_t)NN * HF];
__device__ __align__(16) float4 g_w4[EE];                // per-edge logits -> weights
__device__ __align__(16) __nv_bfloat16 g_Ahi[(size_t)NN * IN_F];
__device__ __align__(16) __nv_bfloat16 g_Alo[(size_t)NN * IN_F];
__device__ __align__(16) __nv_bfloat16 g_Bhi[HC * IN_F];
__device__ __align__(16) __nv_bfloat16 g_Blo[HC * IN_F];
__device__ int   g_deg[NN];
__device__ int   g_rowptr[NN + 1];
__device__ int   g_cursor[NN];
__device__ int   g_csr[EE];
__device__ int   g_is64;

__device__ __forceinline__ float lrelu(float v) { return v > 0.f ? v : NEG_SLOPE * v; }

// ---------------- edge dtype detection ----------------
__global__ void k_flag_init() { g_is64 = 1; }

__global__ void k_detect(const long long* __restrict__ ei) {
    int e = blockIdx.x * blockDim.x + threadIdx.x;
    if (e < EE) {
        long long v = ei[e];
        if (v < 0 || v >= NN) g_is64 = 0;
    }
}

// ---------------- CSR build ----------------
__global__ void k_zero_deg() {
    int i = blockIdx.x * blockDim.x + threadIdx.x;
    if (i < NN) g_deg[i] = 0;
}

__global__ void k_hist(const void* __restrict__ eiv) {
    int e = blockIdx.x * blockDim.x + threadIdx.x;
    if (e < EE) {
        int d = g_is64 ? (int)((const long long*)eiv)[EE + e]
                       : ((const int*)eiv)[EE + e];
        if ((unsigned)d < NN) atomicAdd(&g_deg[d], 1);
    }
}

__global__ void k_scan() {
    __shared__ int sm[1024];
    const int t = threadIdx.x;
    const int CH = (NN + 1023) / 1024;
    const int base = t * CH;
    int s = 0;
    for (int i = 0; i < CH; i++) {
        int idx = base + i;
        if (idx < NN) s += g_deg[idx];
    }
    sm[t] = s;
    __syncthreads();
    for (int off = 1; off < 1024; off <<= 1) {
        int v = (t >= off) ? sm[t - off] : 0;
        __syncthreads();
        sm[t] += v;
        __syncthreads();
    }
    int run = (t > 0) ? sm[t - 1] : 0;
    for (int i = 0; i < CH; i++) {
        int idx = base + i;
        if (idx < NN) { g_rowptr[idx] = run; run += g_deg[idx]; }
    }
    if (t == 0) g_rowptr[NN] = sm[1023];
}

__global__ void k_init_cursor() {
    int i = blockIdx.x * blockDim.x + threadIdx.x;
    if (i < NN) g_cursor[i] = g_rowptr[i];
}

__global__ void k_scatter(const void* __restrict__ eiv) {
    int e = blockIdx.x * blockDim.x + threadIdx.x;
    if (e < EE) {
        int s, d;
        if (g_is64) {
            s = (int)((const long long*)eiv)[e];
            d = (int)((const long long*)eiv)[EE + e];
        } else {
            s = ((const int*)eiv)[e];
            d = ((const int*)eiv)[EE + e];
        }
        if ((unsigned)s < NN && (unsigned)d < NN) {
            int p = atomicAdd(&g_cursor[d], 1);
            g_csr[p] = s;
        }
    }
}

// ---------------- fp32 -> split bf16 conversion ----------------
// DST 0 -> g_Ahi/g_Alo, DST 1 -> g_Bhi/g_Blo. FROM_MID: src = g_mid.
template <int DST, bool FROM_MID>
__global__ void k_cvt(const float* __restrict__ srcp, int n4) {
    int i = blockIdx.x * blockDim.x + threadIdx.x;
    if (i >= n4) return;
    const float4* src = FROM_MID ? (const float4*)g_mid : (const float4*)srcp;
    __nv_bfloat162* hi = (__nv_bfloat162*)(DST == 0 ? g_Ahi : g_Bhi);
    __nv_bfloat162* lo = (__nv_bfloat162*)(DST == 0 ? g_Alo : g_Blo);
    float4 v = src[i];
    __nv_bfloat16 hx = __float2bfloat16_rn(v.x);
    __nv_bfloat16 hy = __float2bfloat16_rn(v.y);
    __nv_bfloat16 hz = __float2bfloat16_rn(v.z);
    __nv_bfloat16 hw = __float2bfloat16_rn(v.w);
    __nv_bfloat16 lx = __float2bfloat16_rn(v.x - __bfloat162float(hx));
    __nv_bfloat16 ly = __float2bfloat16_rn(v.y - __bfloat162float(hy));
    __nv_bfloat16 lz = __float2bfloat16_rn(v.z - __bfloat162float(hz));
    __nv_bfloat16 lw = __float2bfloat16_rn(v.w - __bfloat162float(hw));
    hi[2 * i]     = __halves2bfloat162(hx, hy);
    hi[2 * i + 1] = __halves2bfloat162(hz, hw);
    lo[2 * i]     = __halves2bfloat162(lx, ly);
    lo[2 * i + 1] = __halves2bfloat162(lz, lw);
}

// ---------------- tensor-core GEMM: g_h[M,256] = A * B^T (split bf16) ----------
__device__ __forceinline__ void mma16816(float* c, const uint32_t* a, uint32_t b0, uint32_t b1) {
    asm volatile(
        "mma.sync.aligned.m16n8k16.row.col.f32.bf16.bf16.f32 "
        "{%0,%1,%2,%3},{%4,%5,%6,%7},{%8,%9},{%0,%1,%2,%3};"
        : "+f"(c[0]), "+f"(c[1]), "+f"(c[2]), "+f"(c[3])
        : "r"(a[0]), "r"(a[1]), "r"(a[2]), "r"(a[3]), "r"(b0), "r"(b1));
}

template <int KF>
__global__ void __launch_bounds__(256) k_mma() {
    __shared__ __align__(16) __nv_bfloat16 Ah[128][40], Al[128][40];
    __shared__ __align__(16) __nv_bfloat16 Bh[128][40], Bl[128][40];
    const int t = threadIdx.x;
    const int bm = blockIdx.x * 128, bn = blockIdx.y * 128;
    const int warp = t >> 5, lane = t & 31;
    const int wr = (warp & 1) * 64, wc = (warp >> 1) * 32;
    const int g = lane >> 2, tg = (lane & 3) * 2;

    float acc[4][4][4];
#pragma unroll
    for (int a = 0; a < 4; a++)
#pragma unroll
        for (int b = 0; b < 4; b++)
#pragma unroll
            for (int c = 0; c < 4; c++) acc[a][b][c] = 0.f;

    for (int k0 = 0; k0 < KF; k0 += 32) {
#pragma unroll
        for (int u = t; u < 512; u += 256) {
            int r = u >> 2, cg = (u & 3) * 8;
            uint4 vh = make_uint4(0, 0, 0, 0), vl = vh;
            int gm = bm + r;
            if (gm < NN) {
                vh = *(const uint4*)&g_Ahi[(size_t)gm * KF + k0 + cg];
                vl = *(const uint4*)&g_Alo[(size_t)gm * KF + k0 + cg];
            }
            *(uint4*)&Ah[r][cg] = vh;
            *(uint4*)&Al[r][cg] = vl;
            *(uint4*)&Bh[r][cg] = *(const uint4*)&g_Bhi[(size_t)(bn + r) * KF + k0 + cg];
            *(uint4*)&Bl[r][cg] = *(const uint4*)&g_Blo[(size_t)(bn + r) * KF + k0 + cg];
        }
        __syncthreads();
#pragma unroll
        for (int kk = 0; kk < 32; kk += 16) {
            uint32_t ah[4][4], al[4][4];
#pragma unroll
            for (int mt = 0; mt < 4; mt++) {
                int r0 = wr + mt * 16 + g;
                ah[mt][0] = *(const uint32_t*)&Ah[r0][kk + tg];
                ah[mt][1] = *(const uint32_t*)&Ah[r0 + 8][kk + tg];
                ah[mt][2] = *(const uint32_t*)&Ah[r0][kk + tg + 8];
                ah[mt][3] = *(const uint32_t*)&Ah[r0 + 8][kk + tg + 8];
                al[mt][0] = *(const uint32_t*)&Al[r0][kk + tg];
                al[mt][1] = *(const uint32_t*)&Al[r0 + 8][kk + tg];
                al[mt][2] = *(const uint32_t*)&Al[r0][kk + tg + 8];
                al[mt][3] = *(const uint32_t*)&Al[r0 + 8][kk + tg + 8];
            }
#pragma unroll
            for (int nt = 0; nt < 4; nt++) {
                int c0 = wc + nt * 8 + g;
                uint32_t bh0 = *(const uint32_t*)&Bh[c0][kk + tg];
                uint32_t bh1 = *(const uint32_t*)&Bh[c0][kk + tg + 8];
                uint32_t bl0 = *(const uint32_t*)&Bl[c0][kk + tg];
                uint32_t bl1 = *(const uint32_t*)&Bl[c0][kk + tg + 8];
#pragma unroll
                for (int mt = 0; mt < 4; mt++) {
                    mma16816(acc[mt][nt], ah[mt], bh0, bh1);
                    mma16816(acc[mt][nt], ah[mt], bl0, bl1);
                    mma16816(acc[mt][nt], al[mt], bh0, bh1);
                }
            }
        }
        __syncthreads();
    }
#pragma unroll
    for (int mt = 0; mt < 4; mt++) {
        int r0 = bm + wr + mt * 16 + g;
#pragma unroll
        for (int nt = 0; nt < 4; nt++) {
            int col = bn + wc + nt * 8 + tg;
            if (r0 < NN)
                *(float2*)&g_h[(size_t)r0 * HC + col] = make_float2(acc[mt][nt][0], acc[mt][nt][1]);
            if (r0 + 8 < NN)
                *(float2*)&g_h[(size_t)(r0 + 8) * HC + col] = make_float2(acc[mt][nt][2], acc[mt][nt][3]);
        }
    }
}

// ---------------- attention coefficients ----------------
__global__ void k_attn_coef(const float* __restrict__ a_src, const float* __restrict__ a_dst) {
    int warp = (blockIdx.x * blockDim.x + threadIdx.x) >> 5;
    if (warp >= NN) return;
    int lane = threadIdx.x & 31;
    const float4* hp = (const float4*)&g_h[(size_t)warp * HC];
    float4 v0 = hp[lane * 2], v1 = hp[lane * 2 + 1];
    const float4* ap = (const float4*)a_src;
    const float4* bp = (const float4*)a_dst;
    float4 a0 = ap[lane * 2], a1 = ap[lane * 2 + 1];
    float4 b0 = bp[lane * 2], b1 = bp[lane * 2 + 1];
    float s = v0.x * a0.x + v0.y * a0.y + v0.z * a0.z + v0.w * a0.w
            + v1.x * a1.x + v1.y * a1.y + v1.z * a1.z + v1.w * a1.w;
    float d = v0.x * b0.x + v0.y * b0.y + v0.z * b0.z + v0.w * b0.w
            + v1.x * b1.x + v1.y * b1.y + v1.z * b1.z + v1.w * b1.w;
#pragma unroll
    for (int off = 4; off; off >>= 1) {
        s += __shfl_down_sync(0xffffffffu, s, off);
        d += __shfl_down_sync(0xffffffffu, d, off);
    }
    if ((lane & 7) == 0) {
        int h = lane >> 3;
        g_as[warp * 4 + h] = s;
        g_ad[warp * 4 + h] = d;
    }
}

// ---------------- aggregation: softmax weights to scratch, then gather -------
template <bool TO_OUT>
__global__ void k_aggregate(const float* __restrict__ bias, float* __restrict__ out) {
    int warp = (blockIdx.x * blockDim.x + threadIdx.x) >> 5;
    if (warp >= NN) return;
    const int n = warp;
    const int l = threadIdx.x & 31;
    const int beg = g_rowptr[n];
    const int dr  = g_rowptr[n + 1] - beg;       // real edges (self handled logically)
    const float4 adn = *(const float4*)&g_ad[n * 4];
    const float4 asn = *(const float4*)&g_as[n * 4];

    float4 es;  // self-loop logit
    es.x = lrelu(asn.x + adn.x); es.y = lrelu(asn.y + adn.y);
    es.z = lrelu(asn.z + adn.z); es.w = lrelu(asn.w + adn.w);

    // pass A: gather alpha once, store logits, track max
    float m0 = es.x, m1 = es.y, m2 = es.z, m3 = es.w;
    for (int i = l; i < dr; i += 32) {
        int s = g_csr[beg + i];
        float4 av = *(const float4*)&g_as[s * 4];
        float4 e;
        e.x = lrelu(av.x + adn.x); e.y = lrelu(av.y + adn.y);
        e.z = lrelu(av.z + adn.z); e.w = lrelu(av.w + adn.w);
        g_w4[beg + i] = e;
        m0 = fmaxf(m0, e.x); m1 = fmaxf(m1, e.y);
        m2 = fmaxf(m2, e.z); m3 = fmaxf(m3, e.w);
    }
#pragma unroll
    for (int off = 16; off; off >>= 1) {
        m0 = fmaxf(m0, __shfl_xor_sync(0xffffffffu, m0, off));
        m1 = fmaxf(m1, __shfl_xor_sync(0xffffffffu, m1, off));
        m2 = fmaxf(m2, __shfl_xor_sync(0xffffffffu, m2, off));
        m3 = fmaxf(m3, __shfl_xor_sync(0xffffffffu, m3, off));
    }
    __syncwarp();

    // pass B: exponentiate in place, accumulate denominator
    float d0 = 0.f, d1 = 0.f, d2 = 0.f, d3 = 0.f;
    for (int i = l; i < dr; i += 32) {
        float4 e = g_w4[beg + i];
        e.x = __expf(e.x - m0); e.y = __expf(e.y - m1);
        e.z = __expf(e.z - m2); e.w = __expf(e.w - m3);
        g_w4[beg + i] = e;
        d0 += e.x; d1 += e.y; d2 += e.z; d3 += e.w;
    }
#pragma unroll
    for (int off = 16; off; off >>= 1) {
        d0 += __shfl_xor_sync(0xffffffffu, d0, off);
        d1 += __shfl_xor_sync(0xffffffffu, d1, off);
        d2 += __shfl_xor_sync(0xffffffffu, d2, off);
        d3 += __shfl_xor_sync(0xffffffffu, d3, off);
    }
    es.x = __expf(es.x - m0); es.y = __expf(es.y - m1);
    es.z = __expf(es.z - m2); es.w = __expf(es.w - m3);
    d0 += es.x; d1 += es.y; d2 += es.z; d3 += es.w;
    const float r0 = 1.f / (d0 + 1e-16f), r1 = 1.f / (d1 + 1e-16f);
    const float r2 = 1.f / (d2 + 1e-16f), r3 = 1.f / (d3 + 1e-16f);
    __syncwarp();

    // pass C: weighted gather. Lane owns channels [4l..4l+3] and [128+4l..+3].
    const bool loh = (l < 16);
    const float ra = loh ? r0 : r1;        // head 0 or 1
    const float rb = loh ? r2 : r3;        // head 2 or 3
    const int ca = 4 * l, cb = 128 + 4 * l;
    float4 accA = make_float4(0.f, 0.f, 0.f, 0.f);
    float4 accB = make_float4(0.f, 0.f, 0.f, 0.f);
#pragma unroll 2
    for (int i = 0; i < dr; i++) {
        int s = g_csr[beg + i];                         // broadcast
        float4 w = g_w4[beg + i];                       // broadcast, sequential
        float wa = (loh ? w.x : w.y) * ra;
        float wb = (loh ? w.z : w.w) * rb;
        const float4 ha = *(const float4*)&g_h[(size_t)s * HC + ca];
        const float4 hb = *(const float4*)&g_h[(size_t)s * HC + cb];
        accA.x = fmaf(wa, ha.x, accA.x); accA.y = fmaf(wa, ha.y, accA.y);
        accA.z = fmaf(wa, ha.z, accA.z); accA.w = fmaf(wa, ha.w, accA.w);
        accB.x = fmaf(wb, hb.x, accB.x); accB.y = fmaf(wb, hb.y, accB.y);
        accB.z = fmaf(wb, hb.z, accB.z); accB.w = fmaf(wb, hb.w, accB.w);
    }
    {   // self loop
        float wa = (loh ? es.x : es.y) * ra;
        float wb = (loh ? es.z : es.w) * rb;
        const float4 ha = *(const float4*)&g_h[(size_t)n * HC + ca];
        const float4 hb = *(const float4*)&g_h[(size_t)n * HC + cb];
        accA.x = fmaf(wa, ha.x, accA.x); accA.y = fmaf(wa, ha.y, accA.y);
        accA.z = fmaf(wa, ha.z, accA.z); accA.w = fmaf(wa, ha.w, accA.w);
        accB.x = fmaf(wb, hb.x, accB.x); accB.y = fmaf(wb, hb.y, accB.y);
        accB.z = fmaf(wb, hb.z, accB.z); accB.w = fmaf(wb, hb.w, accB.w);
    }
    // combine heads: lane l (<16) holds heads 0,2; lane l+16 holds 1,3 for same out chans
    float4 sum;
    sum.x = accA.x + accB.x; sum.y = accA.y + accB.y;
    sum.z = accA.z + accB.z; sum.w = accA.w + accB.w;
    sum.x += __shfl_xor_sync(0xffffffffu, sum.x, 16);
    sum.y += __shfl_xor_sync(0xffffffffu, sum.y, 16);
    sum.z += __shfl_xor_sync(0xffffffffu, sum.z, 16);
    sum.w += __shfl_xor_sync(0xffffffffu, sum.w, 16);
    if (loh) {
        const float4 b4 = *(const float4*)&bias[4 * l];
        float4 o;
        o.x = sum.x * 0.25f + b4.x; o.y = sum.y * 0.25f + b4.y;
        o.z = sum.z * 0.25f + b4.z; o.w = sum.w * 0.25f + b4.w;
        if (!TO_OUT) {
            o.x = o.x > 0.f ? o.x : expm1f(o.x);
            o.y = o.y > 0.f ? o.y : expm1f(o.y);
            o.z = o.z > 0.f ? o.z : expm1f(o.z);
            o.w = o.w > 0.f ? o.w : expm1f(o.w);
            *(float4*)&g_mid[(size_t)n * HF + 4 * l] = o;
        } else {
            *(float4*)&out[(size_t)n * HF + 4 * l] = o;
        }
    }
}

// ---------------- host launcher ----------------
extern "C" void kernel_launch(void* const* d_in, const int* in_sizes, int n_in,
                              void* d_out, int out_size) {
    const float* x   = (const float*)d_in[0];
    const void*  ei  = d_in[1];
    const float* W1  = (const float*)d_in[2];
    const float* as1 = (const float*)d_in[3];
    const float* ad1 = (const float*)d_in[4];
    const float* b1  = (const float*)d_in[5];
    const float* W2  = (const float*)d_in[6];
    const float* as2 = (const float*)d_in[7];
    const float* ad2 = (const float*)d_in[8];
    const float* b2  = (const float*)d_in[9];
    float*       out = (float*)d_out;

    // CSR build
    k_flag_init<<<1, 1>>>();
    k_detect<<<(EE + 255) / 256, 256>>>((const long long*)ei);
    k_zero_deg<<<(NN + 255) / 256, 256>>>();
    k_hist<<<(EE + 255) / 256, 256>>>(ei);
    k_scan<<<1, 1024>>>();
    k_init_cursor<<<(NN + 255) / 256, 256>>>();
    k_scatter<<<(EE + 255) / 256, 256>>>(ei);

    const dim3 gemm_grid((NN + 127) / 128, 2);
    const int  warps_grid = (NN * 32 + 255) / 256;

    // layer 1
    {
        int n4a = NN * IN_F / 4, n4b = HC * IN_F / 4;
        k_cvt<0, false><<<(n4a + 255) / 256, 256>>>(x, n4a);
        k_cvt<1, false><<<(n4b + 255) / 256, 256>>>(W1, n4b);
    }
    k_mma<IN_F><<<gemm_grid, 256>>>();
    k_attn_coef<<<warps_grid, 256>>>(as1, ad1);
    k_aggregate<false><<<warps_grid, 256>>>(b1, nullptr);

    // layer 2
    {
        int n4a = NN * HF / 4, n4b = HC * HF / 4;
        k_cvt<0, true><<<(n4a + 255) / 256, 256>>>(nullptr, n4a);
        k_cvt<1, false><<<(n4b + 255) / 256, 256>>>(W2, n4b);
    }
    k_mma<HF><<<gemm_grid, 256>>>();
    k_attn_coef<<<warps_grid, 256>>>(as2, ad2);
    k_aggregate<true><<<warps_grid, 256>>>(b2, out);
}